// round 4
// baseline (speedup 1.0000x reference)
#include <cuda_runtime.h>

#define Bc    256
#define Sc    196
#define RNNc  1024
#define ATTHc 512
#define SPLITK 8
#define KCHUNK 128   // 1024 / SPLITK
#define BK 16
#define LDT 68       // padded shared leading dim (16B-aligned rows, conflict-reduced)

// split-K partial accumulators for att_h = h @ W^T  (4 MB scratch)
__device__ float g_part[SPLITK * Bc * ATTHc];

// ---------------------------------------------------------------------------
// K1: split-K tiled GEMM: partial[z][b][a] = sum_{k in chunk z} h[b][k]*W[a][k]
// Tile 64(b) x 64(a), BK=16, 256 threads, 4x4 microtile per thread.
// ---------------------------------------------------------------------------
__global__ __launch_bounds__(256) void gemm_h2att(const float* __restrict__ h,
                                                  const float* __restrict__ w) {
    __shared__ float hs[BK][LDT];
    __shared__ float ws[BK][LDT];

    const int b0  = blockIdx.x * 64;
    const int a0  = blockIdx.y * 64;
    const int kk0 = blockIdx.z * KCHUNK;
    const int t   = threadIdx.x;

    const int ldr = t >> 2;          // 0..63 : row (b or a) being loaded
    const int ldk = (t & 3) * 4;     // 0,4,8,12 : k offset being loaded

    const int row = t >> 4;          // 0..15 -> b microtile base = row*4
    const int col = t & 15;          // 0..15 -> a microtile base = col*4

    float acc[4][4];
#pragma unroll
    for (int i = 0; i < 4; i++)
#pragma unroll
        for (int j = 0; j < 4; j++) acc[i][j] = 0.f;

    for (int kc = 0; kc < KCHUNK; kc += BK) {
        const float4 hv = *(const float4*)&h[(size_t)(b0 + ldr) * RNNc + kk0 + kc + ldk];
        const float4 wv = *(const float4*)&w[(size_t)(a0 + ldr) * RNNc + kk0 + kc + ldk];
        __syncthreads();   // previous iter's reads complete before overwrite
        hs[ldk + 0][ldr] = hv.x; hs[ldk + 1][ldr] = hv.y;
        hs[ldk + 2][ldr] = hv.z; hs[ldk + 3][ldr] = hv.w;
        ws[ldk + 0][ldr] = wv.x; ws[ldk + 1][ldr] = wv.y;
        ws[ldk + 2][ldr] = wv.z; ws[ldk + 3][ldr] = wv.w;
        __syncthreads();
#pragma unroll
        for (int k = 0; k < BK; k++) {
            const float4 hq = *(const float4*)&hs[k][row * 4];
            const float4 wq = *(const float4*)&ws[k][col * 4];
            const float hb[4] = {hq.x, hq.y, hq.z, hq.w};
            const float wa[4] = {wq.x, wq.y, wq.z, wq.w};
#pragma unroll
            for (int i = 0; i < 4; i++)
#pragma unroll
                for (int j = 0; j < 4; j++) acc[i][j] = fmaf(hb[i], wa[j], acc[i][j]);
        }
    }

    float* dst = g_part + (size_t)blockIdx.z * (Bc * ATTHc)
               + (size_t)(b0 + row * 4) * ATTHc + (a0 + col * 4);
#pragma unroll
    for (int i = 0; i < 4; i++) {
        float4 o; o.x = acc[i][0]; o.y = acc[i][1]; o.z = acc[i][2]; o.w = acc[i][3];
        *(float4*)(dst + (size_t)i * ATTHc) = o;
    }
}

// fast accurate tanh: 2 MUFU (EX2, RCP) + few ALU, ~1e-6 error
__device__ __forceinline__ float fast_tanh(float x) {
    const float xc = fminf(fmaxf(x, -15.f), 15.f);
    const float t  = __expf(2.f * xc);
    return __fdividef(t - 1.f, t + 1.f);
}

// ---------------------------------------------------------------------------
// K2: one block per batch. Reduce split-K partials + bias into shared att_h,
// compute scores with fused tanh, softmax over S, weighted sum of att_feats.
// ---------------------------------------------------------------------------
__global__ __launch_bounds__(256) void att_fused(const float* __restrict__ att_feats,
                                                 const float* __restrict__ p_att,
                                                 const float* __restrict__ b_h2att,
                                                 const float* __restrict__ w_alpha,
                                                 float* __restrict__ out) {
    __shared__ float s_ah[ATTHc];
    __shared__ float s_wa[ATTHc];
    __shared__ float s_sc[Sc];
    __shared__ float red[256];

    const int b = blockIdx.x;
    const int t = threadIdx.x;

    // assemble att_h[b][:] = bias + sum of split-K partials (deterministic)
    for (int j = t; j < ATTHc; j += 256) {
        float v = b_h2att[j];
#pragma unroll
        for (int p = 0; p < SPLITK; p++)
            v += g_part[(size_t)p * (Bc * ATTHc) + (size_t)b * ATTHc + j];
        s_ah[j] = v;
        s_wa[j] = w_alpha[j];
    }
    __syncthreads();

    // ---- Phase A: scores[s] = sum_a w_alpha[a] * tanh(p_att[b][s][a] + att_h[a])
    const int warp = t >> 5, lane = t & 31;
    const float4* ah4 = (const float4*)s_ah;
    const float4* wa4 = (const float4*)s_wa;
    for (int s = warp; s < Sc; s += 8) {
        const float4* pr = (const float4*)(p_att + ((size_t)b * Sc + s) * ATTHc);
        float a = 0.f;
#pragma unroll
        for (int i = 0; i < 4; i++) {
            const int j = lane + 32 * i;
            const float4 pv = pr[j];
            const float4 av = ah4[j];
            const float4 wv = wa4[j];
            a += wv.x * fast_tanh(pv.x + av.x);
            a += wv.y * fast_tanh(pv.y + av.y);
            a += wv.z * fast_tanh(pv.z + av.z);
            a += wv.w * fast_tanh(pv.w + av.w);
        }
#pragma unroll
        for (int o = 16; o; o >>= 1) a += __shfl_xor_sync(0xffffffffu, a, o);
        if (lane == 0) s_sc[s] = a;   // b_alpha omitted: uniform shift, softmax-invariant
    }
    __syncthreads();

    // ---- Phase B: softmax over S=196
    const float v = (t < Sc) ? s_sc[t] : -1e30f;
    red[t] = v; __syncthreads();
#pragma unroll
    for (int o = 128; o; o >>= 1) {
        if (t < o) red[t] = fmaxf(red[t], red[t + o]);
        __syncthreads();
    }
    const float mx = red[0];
    __syncthreads();
    const float e = (t < Sc) ? __expf(v - mx) : 0.f;
    red[t] = e; __syncthreads();
#pragma unroll
    for (int o = 128; o; o >>= 1) {
        if (t < o) red[t] += red[t + o];
        __syncthreads();
    }
    const float inv = __fdividef(1.f, red[0]);
    __syncthreads();
    if (t < Sc) s_sc[t] = e * inv;
    __syncthreads();

    // ---- Phase C: out[b][d] = sum_s weight[s] * att_feats[b][s][d], float4 per thread
    const float4* f4 = (const float4*)(att_feats + (size_t)b * Sc * RNNc);
    float4 acc; acc.x = acc.y = acc.z = acc.w = 0.f;
#pragma unroll 4
    for (int s = 0; s < Sc; s++) {
        const float wgt = s_sc[s];
        const float4 fv = f4[(size_t)s * (RNNc / 4) + t];
        acc.x = fmaf(wgt, fv.x, acc.x);
        acc.y = fmaf(wgt, fv.y, acc.y);
        acc.z = fmaf(wgt, fv.z, acc.z);
        acc.w = fmaf(wgt, fv.w, acc.w);
    }
    *(float4*)(out + (size_t)b * RNNc + 4 * t) = acc;
}

extern "C" void kernel_launch(void* const* d_in, const int* in_sizes, int n_in,
                              void* d_out, int out_size) {
    (void)in_sizes; (void)n_in; (void)out_size;
    const float* h         = (const float*)d_in[0];
    const float* att_feats = (const float*)d_in[1];
    const float* p_att     = (const float*)d_in[2];
    const float* w_h2att   = (const float*)d_in[3];
    const float* b_h2att   = (const float*)d_in[4];
    const float* w_alpha   = (const float*)d_in[5];
    // d_in[6] = b_alpha: uniform score shift, softmax-invariant -> unused
    float* out = (float*)d_out;

    dim3 g1(Bc / 64, ATTHc / 64, SPLITK);   // 4 x 8 x 8 = 256 blocks
    gemm_h2att<<<g1, 256>>>(h, w_h2att);
    att_fused<<<Bc, 256>>>(att_feats, p_att, b_h2att, w_alpha, out);
}

// round 5
// speedup vs baseline: 1.4673x; 1.4673x over previous
#include <cuda_runtime.h>

#define Bc    256
#define Sc    196
#define RNNc  1024
#define ATTHc 512
#define SPLITK 8
#define KCHUNK 128   // 1024 / SPLITK
#define BK 16
#define LDT 68       // padded shared leading dim

// split-K partial accumulators for att_h = h @ W^T  (4 MB scratch)
__device__ float g_part[SPLITK * Bc * ATTHc];
// raw attention scores [B, S]
__device__ float g_scores[Bc * Sc];

// ---------------------------------------------------------------------------
// K1: split-K tiled GEMM: partial[z][b][a] = sum_{k in chunk z} h[b][k]*W[a][k]
// ---------------------------------------------------------------------------
__global__ __launch_bounds__(256) void gemm_h2att(const float* __restrict__ h,
                                                  const float* __restrict__ w) {
    __shared__ float hs[BK][LDT];
    __shared__ float ws[BK][LDT];

    const int b0  = blockIdx.x * 64;
    const int a0  = blockIdx.y * 64;
    const int kk0 = blockIdx.z * KCHUNK;
    const int t   = threadIdx.x;

    const int ldr = t >> 2;
    const int ldk = (t & 3) * 4;
    const int row = t >> 4;
    const int col = t & 15;

    float acc[4][4];
#pragma unroll
    for (int i = 0; i < 4; i++)
#pragma unroll
        for (int j = 0; j < 4; j++) acc[i][j] = 0.f;

    for (int kc = 0; kc < KCHUNK; kc += BK) {
        const float4 hv = *(const float4*)&h[(size_t)(b0 + ldr) * RNNc + kk0 + kc + ldk];
        const float4 wv = *(const float4*)&w[(size_t)(a0 + ldr) * RNNc + kk0 + kc + ldk];
        __syncthreads();
        hs[ldk + 0][ldr] = hv.x; hs[ldk + 1][ldr] = hv.y;
        hs[ldk + 2][ldr] = hv.z; hs[ldk + 3][ldr] = hv.w;
        ws[ldk + 0][ldr] = wv.x; ws[ldk + 1][ldr] = wv.y;
        ws[ldk + 2][ldr] = wv.z; ws[ldk + 3][ldr] = wv.w;
        __syncthreads();
#pragma unroll
        for (int k = 0; k < BK; k++) {
            const float4 hq = *(const float4*)&hs[k][row * 4];
            const float4 wq = *(const float4*)&ws[k][col * 4];
            const float hb[4] = {hq.x, hq.y, hq.z, hq.w};
            const float wa[4] = {wq.x, wq.y, wq.z, wq.w};
#pragma unroll
            for (int i = 0; i < 4; i++)
#pragma unroll
                for (int j = 0; j < 4; j++) acc[i][j] = fmaf(hb[i], wa[j], acc[i][j]);
        }
    }

    float* dst = g_part + (size_t)blockIdx.z * (Bc * ATTHc)
               + (size_t)(b0 + row * 4) * ATTHc + (a0 + col * 4);
#pragma unroll
    for (int i = 0; i < 4; i++) {
        float4 o; o.x = acc[i][0]; o.y = acc[i][1]; o.z = acc[i][2]; o.w = acc[i][3];
        *(float4*)(dst + (size_t)i * ATTHc) = o;
    }
}

// fast accurate tanh: 2 MUFU (EX2, RCP), ~1e-6 error
__device__ __forceinline__ float fast_tanh(float x) {
    const float xc = fminf(fmaxf(x, -15.f), 15.f);
    const float t  = __expf(2.f * xc);
    return __fdividef(t - 1.f, t + 1.f);
}

// ---------------------------------------------------------------------------
// K2: scores[b][s] = sum_a w_alpha[a] * tanh(p_att[b][s][a] + att_h[b][a])
// grid (B, 7): each block handles 28 s-rows; one warp per row (stride 8).
// att_h assembled from split-K partials + bias (L2-resident re-reads, cheap).
// ---------------------------------------------------------------------------
__global__ __launch_bounds__(256) void scores_kernel(const float* __restrict__ p_att,
                                                     const float* __restrict__ b_h2att,
                                                     const float* __restrict__ w_alpha) {
    __shared__ float s_ah[ATTHc];
    __shared__ float s_wa[ATTHc];

    const int b = blockIdx.x;
    const int t = threadIdx.x;

#pragma unroll
    for (int jj = 0; jj < ATTHc / 256; jj++) {
        const int j = t + jj * 256;
        float v = b_h2att[j];
#pragma unroll
        for (int p = 0; p < SPLITK; p++)
            v += g_part[(size_t)p * (Bc * ATTHc) + (size_t)b * ATTHc + j];
        s_ah[j] = v;
        s_wa[j] = w_alpha[j];
    }
    __syncthreads();

    const int warp = t >> 5, lane = t & 31;
    const int sbase = blockIdx.y * 28;
    const float4* ah4 = (const float4*)s_ah;
    const float4* wa4 = (const float4*)s_wa;

    for (int ls = warp; ls < 28; ls += 8) {
        const int s = sbase + ls;
        const float4* pr = (const float4*)(p_att + ((size_t)b * Sc + s) * ATTHc);
        float a = 0.f;
#pragma unroll
        for (int i = 0; i < 4; i++) {
            const int j = lane + 32 * i;
            const float4 pv = pr[j];
            const float4 av = ah4[j];
            const float4 wv = wa4[j];
            a += wv.x * fast_tanh(pv.x + av.x);
            a += wv.y * fast_tanh(pv.y + av.y);
            a += wv.z * fast_tanh(pv.z + av.z);
            a += wv.w * fast_tanh(pv.w + av.w);
        }
#pragma unroll
        for (int o = 16; o; o >>= 1) a += __shfl_xor_sync(0xffffffffu, a, o);
        if (lane == 0) g_scores[b * Sc + s] = a;  // b_alpha: softmax-invariant shift
    }
}

// ---------------------------------------------------------------------------
// K3: grid (B, 2), 128 threads. Recompute softmax (cheap) in shared, then
// stream this block's 512-float D-chunk of att_feats with unroll-8 MLP.
// ---------------------------------------------------------------------------
__global__ __launch_bounds__(128) void wsum_kernel(const float* __restrict__ att_feats,
                                                   float* __restrict__ out) {
    __shared__ float s_w[Sc];
    __shared__ float red[128];

    const int b = blockIdx.x;
    const int t = threadIdx.x;
    const float* sc = g_scores + b * Sc;

    const float v0 = sc[t];                                      // t < 128 < 196
    const float v1 = (t + 128 < Sc) ? sc[t + 128] : -1e30f;
    red[t] = fmaxf(v0, v1);
    __syncthreads();
#pragma unroll
    for (int o = 64; o; o >>= 1) {
        if (t < o) red[t] = fmaxf(red[t], red[t + o]);
        __syncthreads();
    }
    const float mx = red[0];
    __syncthreads();
    const float e0 = __expf(v0 - mx);
    const float e1 = (t + 128 < Sc) ? __expf(v1 - mx) : 0.f;
    red[t] = e0 + e1;
    __syncthreads();
#pragma unroll
    for (int o = 64; o; o >>= 1) {
        if (t < o) red[t] += red[t + o];
        __syncthreads();
    }
    const float inv = __fdividef(1.f, red[0]);
    __syncthreads();
    s_w[t] = e0 * inv;
    if (t + 128 < Sc) s_w[t + 128] = e1 * inv;
    __syncthreads();

    // weighted sum over S for this block's 128 float4 columns
    const float4* f4 = (const float4*)(att_feats + (size_t)b * Sc * RNNc)
                     + (size_t)blockIdx.y * 128 + t;
    float4 acc; acc.x = acc.y = acc.z = acc.w = 0.f;
#pragma unroll 8
    for (int s = 0; s < Sc; s++) {
        const float wgt = s_w[s];
        const float4 fv = f4[(size_t)s * (RNNc / 4)];
        acc.x = fmaf(wgt, fv.x, acc.x);
        acc.y = fmaf(wgt, fv.y, acc.y);
        acc.z = fmaf(wgt, fv.z, acc.z);
        acc.w = fmaf(wgt, fv.w, acc.w);
    }
    ((float4*)out)[(size_t)b * (RNNc / 4) + blockIdx.y * 128 + t] = acc;
}

extern "C" void kernel_launch(void* const* d_in, const int* in_sizes, int n_in,
                              void* d_out, int out_size) {
    (void)in_sizes; (void)n_in; (void)out_size;
    const float* h         = (const float*)d_in[0];
    const float* att_feats = (const float*)d_in[1];
    const float* p_att     = (const float*)d_in[2];
    const float* w_h2att   = (const float*)d_in[3];
    const float* b_h2att   = (const float*)d_in[4];
    const float* w_alpha   = (const float*)d_in[5];
    // d_in[6] = b_alpha: uniform score shift, softmax-invariant -> unused
    float* out = (float*)d_out;

    gemm_h2att<<<dim3(Bc / 64, ATTHc / 64, SPLITK), 256>>>(h, w_h2att);
    scores_kernel<<<dim3(Bc, 7), 256>>>(p_att, b_h2att, w_alpha);
    wsum_kernel<<<dim3(Bc, 2), 128>>>(att_feats, out);
}